// round 2
// baseline (speedup 1.0000x reference)
#include <cuda_runtime.h>
#include <cuda_bf16.h>

#define N_NODES 50000
#define N_EDGES 800000
#define D_FEAT  128

// Scratch (device globals — no allocation allowed)
__device__ float g_h[N_NODES * D_FEAT];       // 25.6 MB, fits in L2
__device__ float g_s1[N_NODES];
__device__ float g_s2[N_NODES];
__device__ int   g_rowptr[N_NODES + 1];
__device__ int   g_edges64;                   // 1 if edges are int64, 0 if int32

// ---------------------------------------------------------------------------
// Probe: detect edge dtype. int64 values < 2^31 have all-zero odd 32-bit
// words; int32 layout puts random dst ids there. Check 1024 odd words.
// ---------------------------------------------------------------------------
__global__ void probe_kernel(const int* __restrict__ w) {
    __shared__ int any_nonzero;
    if (threadIdx.x == 0) any_nonzero = 0;
    __syncthreads();
    // words 1,3,5,...  (first 1024 odd words; buffer has >= 3.2M int32 words
    // if int64, >= 1.6M if int32 — always in bounds)
    if (w[2 * threadIdx.x + 1] != 0) atomicExch(&any_nonzero, 1);
    __syncthreads();
    if (threadIdx.x == 0) g_edges64 = any_nonzero ? 0 : 1;
}

__device__ __forceinline__ int edge_src(const void* edges, int e, int is64) {
    return is64 ? (int)((const long long*)edges)[2 * e]
                : ((const int*)edges)[2 * e];
}
__device__ __forceinline__ int edge_dst(const void* edges, int e, int is64) {
    return is64 ? (int)((const long long*)edges)[2 * e + 1]
                : ((const int*)edges)[2 * e + 1];
}

// ---------------------------------------------------------------------------
// K1: h = X @ W  (50000x128 @ 128x128), fused epilogue computes
//     s1[n] = h[n]·a1, s2[n] = h[n]·a2  (a = kernel_attention split in half).
// ---------------------------------------------------------------------------
__global__ void gemm_s_kernel(const float* __restrict__ x,
                              const float* __restrict__ W,
                              const float* __restrict__ ka) {
    __shared__ float xs[64 * 32];
    __shared__ float Ws[32 * 128];
    const int tid  = threadIdx.x;
    const int lane = tid & 31;
    const int w    = tid >> 5;
    const int row0 = blockIdx.x * 64;

    float acc[8][4];
#pragma unroll
    for (int r = 0; r < 8; r++)
#pragma unroll
        for (int c = 0; c < 4; c++) acc[r][c] = 0.f;

    for (int kc = 0; kc < 4; ++kc) {
        // load X tile 64x32
#pragma unroll
        for (int i = 0; i < 2; i++) {
            int idx = tid * 2 + i;            // 0..511 float4 slots
            int r = idx >> 3;
            int kk = (idx & 7) << 2;
            int grow = row0 + r;
            float4 v = make_float4(0.f, 0.f, 0.f, 0.f);
            if (grow < N_NODES)
                v = *(const float4*)&x[grow * D_FEAT + kc * 32 + kk];
            *(float4*)&xs[r * 32 + kk] = v;
        }
        // load W tile 32x128
#pragma unroll
        for (int i = 0; i < 4; i++) {
            int idx = tid + i * 256;          // 0..1023 float4 slots
            int r = idx >> 5;
            int c = (idx & 31) << 2;
            *(float4*)&Ws[r * 128 + c] = *(const float4*)&W[(kc * 32 + r) * 128 + c];
        }
        __syncthreads();
#pragma unroll
        for (int k = 0; k < 32; k++) {
            float4 wv = *(float4*)&Ws[k * 128 + lane * 4];
#pragma unroll
            for (int rr = 0; rr < 8; rr++) {
                float xv = xs[(w * 8 + rr) * 32 + k];
                acc[rr][0] += xv * wv.x;
                acc[rr][1] += xv * wv.y;
                acc[rr][2] += xv * wv.z;
                acc[rr][3] += xv * wv.w;
            }
        }
        __syncthreads();
    }

    float4 a1 = *(const float4*)&ka[lane * 4];
    float4 a2 = *(const float4*)&ka[128 + lane * 4];
#pragma unroll
    for (int rr = 0; rr < 8; rr++) {
        int grow = row0 + w * 8 + rr;
        if (grow < N_NODES) {   // uniform per warp (depends only on w, rr)
            float4 hv = make_float4(acc[rr][0], acc[rr][1], acc[rr][2], acc[rr][3]);
            *(float4*)&g_h[grow * D_FEAT + lane * 4] = hv;
            float p1 = hv.x * a1.x + hv.y * a1.y + hv.z * a1.z + hv.w * a1.w;
            float p2 = hv.x * a2.x + hv.y * a2.y + hv.z * a2.z + hv.w * a2.w;
#pragma unroll
            for (int o = 16; o > 0; o >>= 1) {
                p1 += __shfl_down_sync(0xffffffffu, p1, o);
                p2 += __shfl_down_sync(0xffffffffu, p2, o);
            }
            if (lane == 0) { g_s1[grow] = p1; g_s2[grow] = p2; }
        }
    }
}

// ---------------------------------------------------------------------------
// K2: CSR rowptr from sorted src. rowptr[n] = first edge with src >= n.
// ---------------------------------------------------------------------------
__global__ void rowptr_kernel(const void* __restrict__ edges) {
    const int is64 = g_edges64;
    int e = blockIdx.x * blockDim.x + threadIdx.x;
    if (e >= N_EDGES) return;
    int s  = edge_src(edges, e, is64);
    int sp = (e == 0) ? -1 : edge_src(edges, e - 1, is64);
    for (int n = sp + 1; n <= s; ++n) g_rowptr[n] = e;
    if (e == N_EDGES - 1)
        for (int n = s + 1; n <= N_NODES; ++n) g_rowptr[n] = N_EDGES;
}

__device__ __forceinline__ float edge_score(float s1v, float s2v) {
    float l = s1v + s2v;
    l = (l > 0.f) ? l : 0.2f * l;          // leaky_relu(0.2)
    l = fminf(fmaxf(l, -2.f), 2.f);        // clip
    return expf(l);
}

// ---------------------------------------------------------------------------
// K3: one warp per node. Pass 1: softmax denominator (lane-strided over the
// node's edge segment + warp reduce). Pass 2: acc += alpha * h[dst] with each
// lane owning 4 output columns (float4). No atomics anywhere.
// ---------------------------------------------------------------------------
__global__ void agg_kernel(const void* __restrict__ edges,
                           float* __restrict__ out) {
    const int is64 = g_edges64;
    int warp = (blockIdx.x * blockDim.x + threadIdx.x) >> 5;
    int lane = threadIdx.x & 31;
    if (warp >= N_NODES) return;
    const int node = warp;
    const int e0 = g_rowptr[node];
    const int e1 = g_rowptr[node + 1];
    const float s1v = g_s1[node];

    // pass 1: denominator
    float part = 0.f;
    for (int e = e0 + lane; e < e1; e += 32) {
        int d = edge_dst(edges, e, is64);
        part += edge_score(s1v, g_s2[d]);
    }
#pragma unroll
    for (int o = 16; o > 0; o >>= 1)
        part += __shfl_xor_sync(0xffffffffu, part, o);
    float rinv = (e1 > e0) ? (1.0f / part) : 0.f;

    // pass 2: weighted gather-accumulate
    float4 acc = make_float4(0.f, 0.f, 0.f, 0.f);
    for (int e = e0; e < e1; ++e) {
        int d = edge_dst(edges, e, is64);
        float a = edge_score(s1v, g_s2[d]) * rinv;
        float4 v = *(const float4*)&g_h[d * D_FEAT + lane * 4];
        acc.x += a * v.x;
        acc.y += a * v.y;
        acc.z += a * v.z;
        acc.w += a * v.w;
    }
    *(float4*)&out[node * D_FEAT + lane * 4] = acc;
}

// ---------------------------------------------------------------------------
extern "C" void kernel_launch(void* const* d_in, const int* in_sizes, int n_in,
                              void* d_out, int out_size) {
    // Identify inputs by element count (ordering-proof).
    const float* x  = nullptr;   // node_states: 6,400,000 elems
    const void*  ed = nullptr;   // edges:       1,600,000 elems
    const float* W  = nullptr;   // kernel:         16,384 elems
    const float* ka = nullptr;   // kernel_attention:  256 elems
    for (int i = 0; i < n_in; i++) {
        switch (in_sizes[i]) {
            case 6400000: x  = (const float*)d_in[i]; break;
            case 1600000: ed = d_in[i];               break;
            case 16384:   W  = (const float*)d_in[i]; break;
            case 256:     ka = (const float*)d_in[i]; break;
            default: break;
        }
    }
    float* out = (float*)d_out;  // [50000,128] float32

    probe_kernel<<<1, 1024>>>((const int*)ed);
    gemm_s_kernel<<<(N_NODES + 63) / 64, 256>>>(x, W, ka);
    rowptr_kernel<<<(N_EDGES + 255) / 256, 256>>>(ed);
    agg_kernel<<<(N_NODES * 32 + 255) / 256, 256>>>(ed, out);
}

// round 6
// speedup vs baseline: 1.0958x; 1.0958x over previous
#include <cuda_runtime.h>
#include <cuda_bf16.h>
#include <cstdint>

#define N_NODES 50000
#define N_EDGES 800000
#define D_FEAT  128

// Scratch (device globals — no allocation allowed)
__device__ float g_h[N_NODES * D_FEAT];       // 25.6 MB, L2-resident
__device__ float g_s1[N_NODES];
__device__ float g_s2[N_NODES];
__device__ float g_wa1[D_FEAT];
__device__ float g_wa2[D_FEAT];
__device__ int   g_rowptr[N_NODES + 1];
__device__ int   g_edges64;                   // 1 if edges are int64, 0 if int32

// ---------------------------------------------------------------------------
// Probe: detect edge dtype. int64 values < 2^31 have all-zero odd 32-bit
// words; int32 layout puts random dst ids there.
// ---------------------------------------------------------------------------
__global__ void probe_kernel(const int* __restrict__ w) {
    __shared__ int any_nonzero;
    if (threadIdx.x == 0) any_nonzero = 0;
    __syncthreads();
    if (w[2 * threadIdx.x + 1] != 0) atomicExch(&any_nonzero, 1);
    __syncthreads();
    if (threadIdx.x == 0) g_edges64 = any_nonzero ? 0 : 1;
}

// ---------------------------------------------------------------------------
// CSR rowptr from sorted src. rowptr[n] = first edge with src >= n.
// ---------------------------------------------------------------------------
__global__ void rowptr_kernel(const int* __restrict__ ew) {
    const int is64 = g_edges64;
    const int stride = is64 ? 4 : 2;
    int e = blockIdx.x * blockDim.x + threadIdx.x;
    if (e >= N_EDGES) return;
    int s  = ew[e * stride];
    int sp = (e == 0) ? -1 : ew[(e - 1) * stride];
    for (int n = sp + 1; n <= s; ++n) g_rowptr[n] = e;
    if (e == N_EDGES - 1)
        for (int n = s + 1; n <= N_NODES; ++n) g_rowptr[n] = N_EDGES;
}

// ---------------------------------------------------------------------------
// wa: wa1 = W @ a1, wa2 = W @ a2  (so s = x · wa, exact fp32, no h needed)
// ---------------------------------------------------------------------------
__global__ void wa_kernel(const float* __restrict__ W,
                          const float* __restrict__ ka) {
    int k = threadIdx.x;   // 0..127
    float s1 = 0.f, s2 = 0.f;
    for (int u = 0; u < D_FEAT; ++u) {
        float w = W[k * D_FEAT + u];
        s1 += w * ka[u];
        s2 += w * ka[D_FEAT + u];
    }
    g_wa1[k] = s1;
    g_wa2[k] = s2;
}

// ---------------------------------------------------------------------------
// s: one warp per node. Each lane covers dims lane, lane+32, lane+64, lane+96
// (ALL 128 dims — R3 bug covered only half). Exact fp32.
// ---------------------------------------------------------------------------
__global__ void s_kernel(const float* __restrict__ x) {
    int t = blockIdx.x * blockDim.x + threadIdx.x;
    int warp = t >> 5, lane = t & 31;
    if (warp >= N_NODES) return;
    const float* xr = x + warp * D_FEAT;
    float p1 = 0.f, p2 = 0.f;
#pragma unroll
    for (int j = 0; j < 4; ++j) {
        float xv = xr[j * 32 + lane];
        p1 += xv * g_wa1[j * 32 + lane];
        p2 += xv * g_wa2[j * 32 + lane];
    }
#pragma unroll
    for (int o = 16; o > 0; o >>= 1) {
        p1 += __shfl_xor_sync(0xffffffffu, p1, o);
        p2 += __shfl_xor_sync(0xffffffffu, p2, o);
    }
    if (lane == 0) { g_s1[warp] = p1; g_s2[warp] = p2; }
}

// ---------------------------------------------------------------------------
// GEMM: h = X @ W via tf32 mma.sync.m16n8k8 (tensor pipe).
// Block 256 thr = 8 warps (2 M x 4 N). Block tile 128x128, K-chunks of 32.
// PTX ISA fragment layout for m16n8k8 tf32 (g=lane>>2, tig=lane&3):
//   a0=(g,tig) a1=(g+8,tig) a2=(g,tig+4) a3=(g+8,tig+4)
//   b0=(k=tig,n=g) b1=(k=tig+4,n=g)
//   c0=(g,2tig) c1=(g,2tig+1) c2=(g+8,2tig) c3=(g+8,2tig+1)
// ---------------------------------------------------------------------------
#define BM 128
#define BK 32
#define XS_STRIDE 40    // A 32-bit LDS: banks 8g+tig all distinct
#define WS_STRIDE 136   // B 32-bit LDS: banks 8tig+g all distinct

__device__ __forceinline__ uint32_t f2tf(float f) {
    uint32_t r;
    asm("cvt.rna.tf32.f32 %0, %1;" : "=r"(r) : "f"(f));
    return r;
}

__device__ __forceinline__ void mma_tf32(float c[4], uint32_t a0, uint32_t a1,
                                         uint32_t a2, uint32_t a3,
                                         uint32_t b0, uint32_t b1) {
    asm volatile(
        "mma.sync.aligned.m16n8k8.row.col.f32.tf32.tf32.f32 "
        "{%0,%1,%2,%3}, {%4,%5,%6,%7}, {%8,%9}, {%0,%1,%2,%3};\n"
        : "+f"(c[0]), "+f"(c[1]), "+f"(c[2]), "+f"(c[3])
        : "r"(a0), "r"(a1), "r"(a2), "r"(a3), "r"(b0), "r"(b1));
}

__global__ __launch_bounds__(256, 1) void gemm_kernel(const float* __restrict__ x,
                                                      const float* __restrict__ W) {
    __shared__ uint32_t Xs[BM * XS_STRIDE];   // 20 KB
    __shared__ uint32_t Ws[BK * WS_STRIDE];   // 17 KB
    const int tid  = threadIdx.x;
    const int lane = tid & 31;
    const int warp = tid >> 5;
    const int wm = warp >> 2;     // 0..1 : M quadrant (64 rows)
    const int wn = warp & 3;      // 0..3 : N quadrant (32 cols)
    const int g   = lane >> 2;    // groupID 0..7
    const int tig = lane & 3;     // threadID_in_group 0..3
    const int row0 = blockIdx.x * BM;

    float c[4][4][4];
#pragma unroll
    for (int mt = 0; mt < 4; mt++)
#pragma unroll
        for (int nt = 0; nt < 4; nt++)
#pragma unroll
            for (int r = 0; r < 4; r++) c[mt][nt][r] = 0.f;

    for (int kc = 0; kc < 4; ++kc) {
        // stage X tile [128 x 32] (tf32-converted)
#pragma unroll
        for (int i = 0; i < 4; i++) {
            int idx = tid + i * 256;
            int r = idx >> 3, c4 = (idx & 7) << 2;
            float4 v = make_float4(0.f, 0.f, 0.f, 0.f);
            if (row0 + r < N_NODES)
                v = *(const float4*)&x[(row0 + r) * D_FEAT + kc * BK + c4];
            uint32_t* p = &Xs[r * XS_STRIDE + c4];
            p[0] = f2tf(v.x); p[1] = f2tf(v.y); p[2] = f2tf(v.z); p[3] = f2tf(v.w);
        }
        // stage W tile [32 x 128]
#pragma unroll
        for (int i = 0; i < 4; i++) {
            int idx = tid + i * 256;
            int r = idx >> 5, c4 = (idx & 31) << 2;
            float4 v = *(const float4*)&W[(kc * BK + r) * D_FEAT + c4];
            uint32_t* p = &Ws[r * WS_STRIDE + c4];
            p[0] = f2tf(v.x); p[1] = f2tf(v.y); p[2] = f2tf(v.z); p[3] = f2tf(v.w);
        }
        __syncthreads();

#pragma unroll
        for (int ks = 0; ks < 4; ++ks) {
            const int k0 = ks * 8;
            uint32_t b[4][2];
#pragma unroll
            for (int nt = 0; nt < 4; nt++) {
                int n = wn * 32 + nt * 8 + g;
                b[nt][0] = Ws[(k0 + tig) * WS_STRIDE + n];
                b[nt][1] = Ws[(k0 + tig + 4) * WS_STRIDE + n];
            }
#pragma unroll
            for (int mt = 0; mt < 4; mt++) {
                int rb = wm * 64 + mt * 16;
                uint32_t a0 = Xs[(rb + g) * XS_STRIDE + k0 + tig];
                uint32_t a1 = Xs[(rb + g + 8) * XS_STRIDE + k0 + tig];
                uint32_t a2 = Xs[(rb + g) * XS_STRIDE + k0 + tig + 4];
                uint32_t a3 = Xs[(rb + g + 8) * XS_STRIDE + k0 + tig + 4];
#pragma unroll
                for (int nt = 0; nt < 4; nt++)
                    mma_tf32(c[mt][nt], a0, a1, a2, a3, b[nt][0], b[nt][1]);
            }
        }
        __syncthreads();
    }

    // epilogue: write h (c0,c1 at row g; c2,c3 at row g+8; cols 2tig,2tig+1)
#pragma unroll
    for (int mt = 0; mt < 4; mt++) {
#pragma unroll
        for (int nt = 0; nt < 4; nt++) {
            int r0 = row0 + wm * 64 + mt * 16 + g;
            int col = wn * 32 + nt * 8 + 2 * tig;
            if (r0 < N_NODES)
                *(float2*)&g_h[r0 * D_FEAT + col] = make_float2(c[mt][nt][0], c[mt][nt][1]);
            if (r0 + 8 < N_NODES)
                *(float2*)&g_h[(r0 + 8) * D_FEAT + col] = make_float2(c[mt][nt][2], c[mt][nt][3]);
        }
    }
}

// ---------------------------------------------------------------------------
// agg: one warp per node, SINGLE pass: accumulate denom and weighted sum
// together, normalize at the end. Unroll-4 for MLP against L2 latency.
// ---------------------------------------------------------------------------
__device__ __forceinline__ float edge_score(float s1v, float s2v) {
    float l = s1v + s2v;
    l = (l > 0.f) ? l : 0.2f * l;          // leaky_relu(0.2)
    l = fminf(fmaxf(l, -2.f), 2.f);        // clip
    return __expf(l);
}

__global__ void agg_kernel(const int* __restrict__ ew,
                           float* __restrict__ out) {
    const int is64 = g_edges64;
    const int stride = is64 ? 4 : 2;
    const int doff   = is64 ? 2 : 1;
    int t = blockIdx.x * blockDim.x + threadIdx.x;
    int node = t >> 5, lane = t & 31;
    if (node >= N_NODES) return;
    const int e0 = g_rowptr[node];
    const int e1 = g_rowptr[node + 1];
    const float s1v = g_s1[node];
    const float* __restrict__ hc = g_h + lane * 4;

    float4 acc = make_float4(0.f, 0.f, 0.f, 0.f);
    float denom = 0.f;
    int e = e0;
    for (; e + 4 <= e1; e += 4) {
        int d0 = ew[(e + 0) * stride + doff];
        int d1 = ew[(e + 1) * stride + doff];
        int d2 = ew[(e + 2) * stride + doff];
        int d3 = ew[(e + 3) * stride + doff];
        float4 v0 = *(const float4*)&hc[d0 * D_FEAT];
        float4 v1 = *(const float4*)&hc[d1 * D_FEAT];
        float4 v2 = *(const float4*)&hc[d2 * D_FEAT];
        float4 v3 = *(const float4*)&hc[d3 * D_FEAT];
        float w0 = edge_score(s1v, g_s2[d0]);
        float w1 = edge_score(s1v, g_s2[d1]);
        float w2 = edge_score(s1v, g_s2[d2]);
        float w3 = edge_score(s1v, g_s2[d3]);
        denom += (w0 + w1) + (w2 + w3);
        acc.x += w0 * v0.x + w1 * v1.x + w2 * v2.x + w3 * v3.x;
        acc.y += w0 * v0.y + w1 * v1.y + w2 * v2.y + w3 * v3.y;
        acc.z += w0 * v0.z + w1 * v1.z + w2 * v2.z + w3 * v3.z;
        acc.w += w0 * v0.w + w1 * v1.w + w2 * v2.w + w3 * v3.w;
    }
    for (; e < e1; ++e) {
        int d = ew[e * stride + doff];
        float w = edge_score(s1v, g_s2[d]);
        float4 v = *(const float4*)&hc[d * D_FEAT];
        denom += w;
        acc.x += w * v.x; acc.y += w * v.y; acc.z += w * v.z; acc.w += w * v.w;
    }
    float rinv = (e1 > e0) ? (1.0f / denom) : 0.f;
    acc.x *= rinv; acc.y *= rinv; acc.z *= rinv; acc.w *= rinv;
    *(float4*)&out[node * D_FEAT + lane * 4] = acc;
}

// ---------------------------------------------------------------------------
extern "C" void kernel_launch(void* const* d_in, const int* in_sizes, int n_in,
                              void* d_out, int out_size) {
    // Identify inputs by element count (ordering-proof).
    const float* x  = nullptr;   // node_states: 6,400,000
    const void*  ed = nullptr;   // edges:       1,600,000
    const float* W  = nullptr;   // kernel:         16,384
    const float* ka = nullptr;   // kernel_attention:  256
    for (int i = 0; i < n_in; i++) {
        switch (in_sizes[i]) {
            case 6400000: x  = (const float*)d_in[i]; break;
            case 1600000: ed = d_in[i];               break;
            case 16384:   W  = (const float*)d_in[i]; break;
            case 256:     ka = (const float*)d_in[i]; break;
            default: break;
        }
    }
    float* out = (float*)d_out;  // [50000,128] float32

    probe_kernel<<<1, 1024>>>((const int*)ed);
    rowptr_kernel<<<(N_EDGES + 255) / 256, 256>>>((const int*)ed);
    wa_kernel<<<1, 128>>>(W, ka);
    s_kernel<<<(N_NODES * 32 + 255) / 256, 256>>>(x);
    gemm_kernel<<<(N_NODES + BM - 1) / BM, 256>>>(x, W);
    agg_kernel<<<(N_NODES * 32 + 255) / 256, 256>>>((const int*)ed, out);
}

// round 7
// speedup vs baseline: 1.1680x; 1.0659x over previous
#include <cuda_runtime.h>
#include <cuda_fp16.h>
#include <cstdint>

#define N_NODES 50000
#define N_EDGES 800000
#define D_FEAT  128

// Scratch (device globals — no allocation allowed)
__device__ __half g_hh[N_NODES * D_FEAT];     // 12.8 MB, L2-resident
__device__ float g_s1[N_NODES];
__device__ float g_s2[N_NODES];
__device__ float g_wa1[D_FEAT];
__device__ float g_wa2[D_FEAT];
__device__ int   g_rowptr[N_NODES + 1];
__device__ int   g_edges64;                   // 1 if edges are int64, 0 if int32

// ---------------------------------------------------------------------------
// init: block 0 = dtype probe (int64 values < 2^31 have all-zero odd words),
//       block 1 = wa1 = W @ a1, wa2 = W @ a2  (exact fp32 attention basis)
// ---------------------------------------------------------------------------
__global__ void init_kernel(const int* __restrict__ w,
                            const float* __restrict__ W,
                            const float* __restrict__ ka) {
    if (blockIdx.x == 0) {
        __shared__ int any_nonzero;
        if (threadIdx.x == 0) any_nonzero = 0;
        __syncthreads();
        if (w[2 * threadIdx.x + 1] != 0) atomicExch(&any_nonzero, 1);
        __syncthreads();
        if (threadIdx.x == 0) g_edges64 = any_nonzero ? 0 : 1;
    } else if (threadIdx.x < D_FEAT) {
        int k = threadIdx.x;
        float s1 = 0.f, s2 = 0.f;
        for (int u = 0; u < D_FEAT; ++u) {
            float wv = W[k * D_FEAT + u];
            s1 += wv * ka[u];
            s2 += wv * ka[D_FEAT + u];
        }
        g_wa1[k] = s1;
        g_wa2[k] = s2;
    }
}

// ---------------------------------------------------------------------------
// CSR rowptr from sorted src. rowptr[n] = first edge with src >= n.
// ---------------------------------------------------------------------------
__global__ void rowptr_kernel(const int* __restrict__ ew) {
    const int is64 = g_edges64;
    const int stride = is64 ? 4 : 2;
    int e = blockIdx.x * blockDim.x + threadIdx.x;
    if (e >= N_EDGES) return;
    int s  = ew[e * stride];
    int sp = (e == 0) ? -1 : ew[(e - 1) * stride];
    for (int n = sp + 1; n <= s; ++n) g_rowptr[n] = e;
    if (e == N_EDGES - 1)
        for (int n = s + 1; n <= N_NODES; ++n) g_rowptr[n] = N_EDGES;
}

// ---------------------------------------------------------------------------
// s: one warp per node, float4 per lane (covers all 128 dims), exact fp32.
// Runs AFTER gemm so x is L2-resident.
// ---------------------------------------------------------------------------
__global__ void s_kernel(const float* __restrict__ x) {
    int t = blockIdx.x * blockDim.x + threadIdx.x;
    int warp = t >> 5, lane = t & 31;
    if (warp >= N_NODES) return;
    float4 xv = *(const float4*)&x[warp * D_FEAT + lane * 4];
    float4 w1 = *(const float4*)&g_wa1[lane * 4];
    float4 w2 = *(const float4*)&g_wa2[lane * 4];
    float p1 = xv.x * w1.x + xv.y * w1.y + xv.z * w1.z + xv.w * w1.w;
    float p2 = xv.x * w2.x + xv.y * w2.y + xv.z * w2.z + xv.w * w2.w;
#pragma unroll
    for (int o = 16; o > 0; o >>= 1) {
        p1 += __shfl_xor_sync(0xffffffffu, p1, o);
        p2 += __shfl_xor_sync(0xffffffffu, p2, o);
    }
    if (lane == 0) { g_s1[warp] = p1; g_s2[warp] = p2; }
}

// ---------------------------------------------------------------------------
// GEMM: h = X @ W via tf32 mma.sync.m16n8k8 (tensor pipe), h stored as fp16.
// PTX ISA fragment layout for m16n8k8 tf32 (g=lane>>2, tig=lane&3):
//   a0=(g,tig) a1=(g+8,tig) a2=(g,tig+4) a3=(g+8,tig+4)
//   b0=(k=tig,n=g) b1=(k=tig+4,n=g)
//   c0=(g,2tig) c1=(g,2tig+1) c2=(g+8,2tig) c3=(g+8,2tig+1)
// ---------------------------------------------------------------------------
#define BM 128
#define BK 32
#define XS_STRIDE 40    // A 32-bit LDS: banks 8g+tig all distinct
#define WS_STRIDE 136   // B 32-bit LDS: banks 8tig+g all distinct

__device__ __forceinline__ uint32_t f2tf(float f) {
    uint32_t r;
    asm("cvt.rna.tf32.f32 %0, %1;" : "=r"(r) : "f"(f));
    return r;
}

__device__ __forceinline__ void mma_tf32(float c[4], uint32_t a0, uint32_t a1,
                                         uint32_t a2, uint32_t a3,
                                         uint32_t b0, uint32_t b1) {
    asm volatile(
        "mma.sync.aligned.m16n8k8.row.col.f32.tf32.tf32.f32 "
        "{%0,%1,%2,%3}, {%4,%5,%6,%7}, {%8,%9}, {%0,%1,%2,%3};\n"
        : "+f"(c[0]), "+f"(c[1]), "+f"(c[2]), "+f"(c[3])
        : "r"(a0), "r"(a1), "r"(a2), "r"(a3), "r"(b0), "r"(b1));
}

__global__ __launch_bounds__(256, 1) void gemm_kernel(const float* __restrict__ x,
                                                      const float* __restrict__ W) {
    __shared__ uint32_t Xs[BM * XS_STRIDE];   // 20 KB
    __shared__ uint32_t Ws[BK * WS_STRIDE];   // 17 KB
    const int tid  = threadIdx.x;
    const int lane = tid & 31;
    const int warp = tid >> 5;
    const int wm = warp >> 2;     // 0..1 : M quadrant (64 rows)
    const int wn = warp & 3;      // 0..3 : N quadrant (32 cols)
    const int g   = lane >> 2;    // groupID 0..7
    const int tig = lane & 3;     // threadID_in_group 0..3
    const int row0 = blockIdx.x * BM;

    float c[4][4][4];
#pragma unroll
    for (int mt = 0; mt < 4; mt++)
#pragma unroll
        for (int nt = 0; nt < 4; nt++)
#pragma unroll
            for (int r = 0; r < 4; r++) c[mt][nt][r] = 0.f;

    for (int kc = 0; kc < 4; ++kc) {
        // stage X tile [128 x 32] (tf32-converted)
#pragma unroll
        for (int i = 0; i < 4; i++) {
            int idx = tid + i * 256;
            int r = idx >> 3, c4 = (idx & 7) << 2;
            float4 v = make_float4(0.f, 0.f, 0.f, 0.f);
            if (row0 + r < N_NODES)
                v = *(const float4*)&x[(row0 + r) * D_FEAT + kc * BK + c4];
            uint32_t* p = &Xs[r * XS_STRIDE + c4];
            p[0] = f2tf(v.x); p[1] = f2tf(v.y); p[2] = f2tf(v.z); p[3] = f2tf(v.w);
        }
        // stage W tile [32 x 128]
#pragma unroll
        for (int i = 0; i < 4; i++) {
            int idx = tid + i * 256;
            int r = idx >> 5, c4 = (idx & 31) << 2;
            float4 v = *(const float4*)&W[(kc * BK + r) * D_FEAT + c4];
            uint32_t* p = &Ws[r * WS_STRIDE + c4];
            p[0] = f2tf(v.x); p[1] = f2tf(v.y); p[2] = f2tf(v.z); p[3] = f2tf(v.w);
        }
        __syncthreads();

#pragma unroll
        for (int ks = 0; ks < 4; ++ks) {
            const int k0 = ks * 8;
            uint32_t b[4][2];
#pragma unroll
            for (int nt = 0; nt < 4; nt++) {
                int n = wn * 32 + nt * 8 + g;
                b[nt][0] = Ws[(k0 + tig) * WS_STRIDE + n];
                b[nt][1] = Ws[(k0 + tig + 4) * WS_STRIDE + n];
            }
#pragma unroll
            for (int mt = 0; mt < 4; mt++) {
                int rb = wm * 64 + mt * 16;
                uint32_t a0 = Xs[(rb + g) * XS_STRIDE + k0 + tig];
                uint32_t a1 = Xs[(rb + g + 8) * XS_STRIDE + k0 + tig];
                uint32_t a2 = Xs[(rb + g) * XS_STRIDE + k0 + tig + 4];
                uint32_t a3 = Xs[(rb + g + 8) * XS_STRIDE + k0 + tig + 4];
#pragma unroll
                for (int nt = 0; nt < 4; nt++)
                    mma_tf32(c[mt][nt], a0, a1, a2, a3, b[nt][0], b[nt][1]);
            }
        }
        __syncthreads();
    }

    // epilogue: write h as fp16 (half2 per c-register pair)
#pragma unroll
    for (int mt = 0; mt < 4; mt++) {
#pragma unroll
        for (int nt = 0; nt < 4; nt++) {
            int r0 = row0 + wm * 64 + mt * 16 + g;
            int col = wn * 32 + nt * 8 + 2 * tig;
            if (r0 < N_NODES)
                *(__half2*)&g_hh[r0 * D_FEAT + col] =
                    __floats2half2_rn(c[mt][nt][0], c[mt][nt][1]);
            if (r0 + 8 < N_NODES)
                *(__half2*)&g_hh[(r0 + 8) * D_FEAT + col] =
                    __floats2half2_rn(c[mt][nt][2], c[mt][nt][3]);
        }
    }
}

// ---------------------------------------------------------------------------
// agg: one warp per node, single pass (denominator + weighted sum together,
// normalize at end). fp16 h gather: 8B per lane per edge. Unroll-4 for MLP.
// ---------------------------------------------------------------------------
__device__ __forceinline__ float edge_score(float s1v, float s2v) {
    float l = s1v + s2v;
    l = (l > 0.f) ? l : 0.2f * l;          // leaky_relu(0.2)
    l = fminf(fmaxf(l, -2.f), 2.f);        // clip
    return __expf(l);
}

__device__ __forceinline__ void acc_edge(float4& acc, float w, uint2 raw) {
    float2 lo = __half22float2(*(__half2*)&raw.x);
    float2 hi = __half22float2(*(__half2*)&raw.y);
    acc.x += w * lo.x; acc.y += w * lo.y;
    acc.z += w * hi.x; acc.w += w * hi.y;
}

__global__ void agg_kernel(const int* __restrict__ ew,
                           float* __restrict__ out) {
    const int is64 = g_edges64;
    const int stride = is64 ? 4 : 2;
    const int doff   = is64 ? 2 : 1;
    int t = blockIdx.x * blockDim.x + threadIdx.x;
    int node = t >> 5, lane = t & 31;
    if (node >= N_NODES) return;
    const int e0 = g_rowptr[node];
    const int e1 = g_rowptr[node + 1];
    const float s1v = g_s1[node];
    const __half* __restrict__ hc = g_hh + lane * 4;

    float4 acc = make_float4(0.f, 0.f, 0.f, 0.f);
    float denom = 0.f;
    int e = e0;
    for (; e + 4 <= e1; e += 4) {
        int d0 = ew[(e + 0) * stride + doff];
        int d1 = ew[(e + 1) * stride + doff];
        int d2 = ew[(e + 2) * stride + doff];
        int d3 = ew[(e + 3) * stride + doff];
        uint2 r0 = *(const uint2*)&hc[d0 * D_FEAT];
        uint2 r1 = *(const uint2*)&hc[d1 * D_FEAT];
        uint2 r2 = *(const uint2*)&hc[d2 * D_FEAT];
        uint2 r3 = *(const uint2*)&hc[d3 * D_FEAT];
        float w0 = edge_score(s1v, g_s2[d0]);
        float w1 = edge_score(s1v, g_s2[d1]);
        float w2 = edge_score(s1v, g_s2[d2]);
        float w3 = edge_score(s1v, g_s2[d3]);
        denom += (w0 + w1) + (w2 + w3);
        acc_edge(acc, w0, r0);
        acc_edge(acc, w1, r1);
        acc_edge(acc, w2, r2);
        acc_edge(acc, w3, r3);
    }
    for (; e < e1; ++e) {
        int d = ew[e * stride + doff];
        float w = edge_score(s1v, g_s2[d]);
        uint2 r = *(const uint2*)&hc[d * D_FEAT];
        denom += w;
        acc_edge(acc, w, r);
    }
    float rinv = (e1 > e0) ? (1.0f / denom) : 0.f;
    acc.x *= rinv; acc.y *= rinv; acc.z *= rinv; acc.w *= rinv;
    *(float4*)&out[node * D_FEAT + lane * 4] = acc;
}

// ---------------------------------------------------------------------------
extern "C" void kernel_launch(void* const* d_in, const int* in_sizes, int n_in,
                              void* d_out, int out_size) {
    // Identify inputs by element count (ordering-proof).
    const float* x  = nullptr;   // node_states: 6,400,000
    const void*  ed = nullptr;   // edges:       1,600,000
    const float* W  = nullptr;   // kernel:         16,384
    const float* ka = nullptr;   // kernel_attention:  256
    for (int i = 0; i < n_in; i++) {
        switch (in_sizes[i]) {
            case 6400000: x  = (const float*)d_in[i]; break;
            case 1600000: ed = d_in[i];               break;
            case 16384:   W  = (const float*)d_in[i]; break;
            case 256:     ka = (const float*)d_in[i]; break;
            default: break;
        }
    }
    float* out = (float*)d_out;  // [50000,128] float32

    init_kernel<<<2, 1024>>>((const int*)ed, W, ka);
    rowptr_kernel<<<(N_EDGES + 255) / 256, 256>>>((const int*)ed);
    gemm_kernel<<<(N_NODES + BM - 1) / BM, 256>>>(x, W);
    s_kernel<<<(N_NODES * 32 + 255) / 256, 256>>>(x);   // x now L2-resident
    agg_kernel<<<(N_NODES * 32 + 255) / 256, 256>>>((const int*)ed, out);
}

// round 9
// speedup vs baseline: 1.4201x; 1.2159x over previous
#include <cuda_runtime.h>
#include <cuda_fp16.h>
#include <cstdint>

#define N_NODES 50000
#define N_EDGES 800000
#define D_FEAT  128

// Scratch (device globals — no allocation allowed)
__device__ __half g_hh[N_NODES * D_FEAT];     // 12.8 MB, L2-resident
__device__ float g_s1[N_NODES];
__device__ float g_s2[N_NODES];
__device__ int   g_rowptr[N_NODES + 1];
__device__ int   g_edges64;                   // 1 if edges are int64, 0 if int32

// ---------------------------------------------------------------------------
// probe: detect edge dtype. int64 values < 2^31 have all-zero odd words.
// ---------------------------------------------------------------------------
__global__ void probe_kernel(const int* __restrict__ w) {
    __shared__ int any_nonzero;
    if (threadIdx.x == 0) any_nonzero = 0;
    __syncthreads();
    if (w[2 * threadIdx.x + 1] != 0) atomicExch(&any_nonzero, 1);
    __syncthreads();
    if (threadIdx.x == 0) g_edges64 = any_nonzero ? 0 : 1;
}

// ---------------------------------------------------------------------------
// CSR rowptr from sorted src. rowptr[n] = first edge with src >= n.
// ---------------------------------------------------------------------------
__global__ void rowptr_kernel(const int* __restrict__ ew) {
    const int is64 = g_edges64;
    const int stride = is64 ? 4 : 2;
    int e = blockIdx.x * blockDim.x + threadIdx.x;
    if (e >= N_EDGES) return;
    int s  = ew[e * stride];
    int sp = (e == 0) ? -1 : ew[(e - 1) * stride];
    for (int n = sp + 1; n <= s; ++n) g_rowptr[n] = e;
    if (e == N_EDGES - 1)
        for (int n = s + 1; n <= N_NODES; ++n) g_rowptr[n] = N_EDGES;
}

// ---------------------------------------------------------------------------
// GEMM: h = X @ W via tf32 mma.sync.m16n8k8 (tensor pipe), h stored as fp16.
// Fused epilogue: s1[row] = h[row]·ka[0:128], s2[row] = h[row]·ka[128:256]
// computed from the fp32 accumulators (h), via quad-shuffle + smem reduce.
// PTX ISA fragment layout for m16n8k8 tf32 (g=lane>>2, tig=lane&3):
//   a0=(g,tig) a1=(g+8,tig) a2=(g,tig+4) a3=(g+8,tig+4)
//   b0=(k=tig,n=g) b1=(k=tig+4,n=g)
//   c0=(g,2tig) c1=(g,2tig+1) c2=(g+8,2tig) c3=(g+8,2tig+1)
// ---------------------------------------------------------------------------
#define BM 128
#define BK 32
#define XS_STRIDE 40    // A 32-bit LDS: banks 8g+tig all distinct
#define WS_STRIDE 136   // B 32-bit LDS: banks 8tig+g all distinct

__device__ __forceinline__ uint32_t f2tf(float f) {
    uint32_t r;
    asm("cvt.rna.tf32.f32 %0, %1;" : "=r"(r) : "f"(f));
    return r;
}

__device__ __forceinline__ void mma_tf32(float c[4], uint32_t a0, uint32_t a1,
                                         uint32_t a2, uint32_t a3,
                                         uint32_t b0, uint32_t b1) {
    asm volatile(
        "mma.sync.aligned.m16n8k8.row.col.f32.tf32.tf32.f32 "
        "{%0,%1,%2,%3}, {%4,%5,%6,%7}, {%8,%9}, {%0,%1,%2,%3};\n"
        : "+f"(c[0]), "+f"(c[1]), "+f"(c[2]), "+f"(c[3])
        : "r"(a0), "r"(a1), "r"(a2), "r"(a3), "r"(b0), "r"(b1));
}

__global__ __launch_bounds__(256, 1) void gemm_kernel(const float* __restrict__ x,
                                                      const float* __restrict__ W,
                                                      const float* __restrict__ ka) {
    __shared__ uint32_t Xs[BM * XS_STRIDE];   // 20 KB
    __shared__ uint32_t Ws[BK * WS_STRIDE];   // 17 KB
    __shared__ float    sp1[4][BM];           // 2 KB  per-warp s1 partials
    __shared__ float    sp2[4][BM];           // 2 KB  per-warp s2 partials
    const int tid  = threadIdx.x;
    const int lane = tid & 31;
    const int warp = tid >> 5;
    const int wm = warp >> 2;     // 0..1 : M quadrant (64 rows)
    const int wn = warp & 3;      // 0..3 : N quadrant (32 cols)
    const int g   = lane >> 2;    // groupID 0..7
    const int tig = lane & 3;     // threadID_in_group 0..3
    const int row0 = blockIdx.x * BM;

    float c[4][4][4];
#pragma unroll
    for (int mt = 0; mt < 4; mt++)
#pragma unroll
        for (int nt = 0; nt < 4; nt++)
#pragma unroll
            for (int r = 0; r < 4; r++) c[mt][nt][r] = 0.f;

    for (int kc = 0; kc < 4; ++kc) {
        // stage X tile [128 x 32] (tf32-converted)
#pragma unroll
        for (int i = 0; i < 4; i++) {
            int idx = tid + i * 256;
            int r = idx >> 3, c4 = (idx & 7) << 2;
            float4 v = make_float4(0.f, 0.f, 0.f, 0.f);
            if (row0 + r < N_NODES)
                v = *(const float4*)&x[(row0 + r) * D_FEAT + kc * BK + c4];
            uint32_t* p = &Xs[r * XS_STRIDE + c4];
            p[0] = f2tf(v.x); p[1] = f2tf(v.y); p[2] = f2tf(v.z); p[3] = f2tf(v.w);
        }
        // stage W tile [32 x 128]
#pragma unroll
        for (int i = 0; i < 4; i++) {
            int idx = tid + i * 256;
            int r = idx >> 5, c4 = (idx & 31) << 2;
            float4 v = *(const float4*)&W[(kc * BK + r) * D_FEAT + c4];
            uint32_t* p = &Ws[r * WS_STRIDE + c4];
            p[0] = f2tf(v.x); p[1] = f2tf(v.y); p[2] = f2tf(v.z); p[3] = f2tf(v.w);
        }
        __syncthreads();

#pragma unroll
        for (int ks = 0; ks < 4; ++ks) {
            const int k0 = ks * 8;
            uint32_t b[4][2];
#pragma unroll
            for (int nt = 0; nt < 4; nt++) {
                int n = wn * 32 + nt * 8 + g;
                b[nt][0] = Ws[(k0 + tig) * WS_STRIDE + n];
                b[nt][1] = Ws[(k0 + tig + 4) * WS_STRIDE + n];
            }
#pragma unroll
            for (int mt = 0; mt < 4; mt++) {
                int rb = wm * 64 + mt * 16;
                uint32_t a0 = Xs[(rb + g) * XS_STRIDE + k0 + tig];
                uint32_t a1 = Xs[(rb + g + 8) * XS_STRIDE + k0 + tig];
                uint32_t a2 = Xs[(rb + g) * XS_STRIDE + k0 + tig + 4];
                uint32_t a3 = Xs[(rb + g + 8) * XS_STRIDE + k0 + tig + 4];
#pragma unroll
                for (int nt = 0; nt < 4; nt++)
                    mma_tf32(c[mt][nt], a0, a1, a2, a3, b[nt][0], b[nt][1]);
            }
        }
        __syncthreads();
    }

    // per-lane attention-vector fragments: s = h · ka  (cols of h ↔ ka rows)
    float2 wa1f[4], wa2f[4];
#pragma unroll
    for (int nt = 0; nt < 4; nt++) {
        int col = wn * 32 + nt * 8 + 2 * tig;
        wa1f[nt] = *(const float2*)&ka[col];           // a1 = ka[0:128]
        wa2f[nt] = *(const float2*)&ka[D_FEAT + col];  // a2 = ka[128:256]
    }

    // epilogue: write h as fp16 + accumulate s partials from fp32 accumulators
#pragma unroll
    for (int mt = 0; mt < 4; mt++) {
        float p1a = 0.f, p2a = 0.f;   // row wm*64+mt*16+g
        float p1b = 0.f, p2b = 0.f;   // row ... +8
#pragma unroll
        for (int nt = 0; nt < 4; nt++) {
            int r0 = row0 + wm * 64 + mt * 16 + g;
            int col = wn * 32 + nt * 8 + 2 * tig;
            if (r0 < N_NODES)
                *(__half2*)&g_hh[r0 * D_FEAT + col] =
                    __floats2half2_rn(c[mt][nt][0], c[mt][nt][1]);
            if (r0 + 8 < N_NODES)
                *(__half2*)&g_hh[(r0 + 8) * D_FEAT + col] =
                    __floats2half2_rn(c[mt][nt][2], c[mt][nt][3]);
            p1a += c[mt][nt][0] * wa1f[nt].x + c[mt][nt][1] * wa1f[nt].y;
            p2a += c[mt][nt][0] * wa2f[nt].x + c[mt][nt][1] * wa2f[nt].y;
            p1b += c[mt][nt][2] * wa1f[nt].x + c[mt][nt][3] * wa1f[nt].y;
            p2b += c[mt][nt][2] * wa2f[nt].x + c[mt][nt][3] * wa2f[nt].y;
        }
        // quad reduce over tig (lanes 4g+tig: xor 1 then 2 stays in quad)
#pragma unroll
        for (int o = 1; o <= 2; o <<= 1) {
            p1a += __shfl_xor_sync(0xffffffffu, p1a, o);
            p2a += __shfl_xor_sync(0xffffffffu, p2a, o);
            p1b += __shfl_xor_sync(0xffffffffu, p1b, o);
            p2b += __shfl_xor_sync(0xffffffffu, p2b, o);
        }
        if (tig == 0) {
            int rl = wm * 64 + mt * 16 + g;
            sp1[wn][rl]     = p1a;  sp2[wn][rl]     = p2a;
            sp1[wn][rl + 8] = p1b;  sp2[wn][rl + 8] = p2b;
        }
    }
    __syncthreads();
    if (tid < BM) {
        int grow = row0 + tid;
        if (grow < N_NODES) {
            g_s1[grow] = sp1[0][tid] + sp1[1][tid] + sp1[2][tid] + sp1[3][tid];
            g_s2[grow] = sp2[0][tid] + sp2[1][tid] + sp2[2][tid] + sp2[3][tid];
        }
    }
}

// ---------------------------------------------------------------------------
// agg: one warp per node, single pass (denominator + weighted sum together,
// normalize at end). fp16 h gather: 8B per lane per edge. Unroll-4 for MLP.
// ---------------------------------------------------------------------------
__device__ __forceinline__ float edge_score(float s1v, float s2v) {
    float l = s1v + s2v;
    l = (l > 0.f) ? l : 0.2f * l;          // leaky_relu(0.2)
    l = fminf(fmaxf(l, -2.f), 2.f);        // clip
    return __expf(l);
}

__device__ __forceinline__ void acc_edge(float4& acc, float w, uint2 raw) {
    float2 lo = __half22float2(*(__half2*)&raw.x);
    float2 hi = __half22float2(*(__half2*)&raw.y);
    acc.x += w * lo.x; acc.y += w * lo.y;
    acc.z += w * hi.x; acc.w += w * hi.y;
}

__global__ void agg_kernel(const int* __restrict__ ew,
                           float* __restrict__ out) {
    const int is64 = g_edges64;
    const int stride = is64 ? 4 : 2;
    const int doff   = is64 ? 2 : 1;
    int t = blockIdx.x * blockDim.x + threadIdx.x;
    int node = t >> 5, lane = t & 31;
    if (node >= N_NODES) return;
    const int e0 = g_rowptr[node];
    const int e1 = g_rowptr[node + 1];
    const float s1v = g_s1[node];
    const __half* __restrict__ hc = g_hh + lane * 4;

    float4 acc = make_float4(0.f, 0.f, 0.f, 0.f);
    float denom = 0.f;
    int e = e0;
    for (; e + 4 <= e1; e += 4) {
        int d0 = ew[(e + 0) * stride + doff];
        int d1 = ew[(e + 1) * stride + doff];
        int d2 = ew[(e + 2) * stride + doff];
        int d3 = ew[(e + 3) * stride + doff];
        uint2 r0 = *(const uint2*)&hc[d0 * D_FEAT];
        uint2 r1 = *(const uint2*)&hc[d1 * D_FEAT];
        uint2 r2 = *(const uint2*)&hc[d2 * D_FEAT];
        uint2 r3 = *(const uint2*)&hc[d3 * D_FEAT];
        float w0 = edge_score(s1v, g_s2[d0]);
        float w1 = edge_score(s1v, g_s2[d1]);
        float w2 = edge_score(s1v, g_s2[d2]);
        float w3 = edge_score(s1v, g_s2[d3]);
        denom += (w0 + w1) + (w2 + w3);
        acc_edge(acc, w0, r0);
        acc_edge(acc, w1, r1);
        acc_edge(acc, w2, r2);
        acc_edge(acc, w3, r3);
    }
    for (; e < e1; ++e) {
        int d = ew[e * stride + doff];
        float w = edge_score(s1v, g_s2[d]);
        uint2 r = *(const uint2*)&hc[d * D_FEAT];
        denom += w;
        acc_edge(acc, w, r);
    }
    float rinv = (e1 > e0) ? (1.0f / denom) : 0.f;
    acc.x *= rinv; acc.y *= rinv; acc.z *= rinv; acc.w *= rinv;
    *(float4*)&out[node * D_FEAT + lane * 4] = acc;
}

// ---------------------------------------------------------------------------
extern "C" void kernel_launch(void* const* d_in, const int* in_sizes, int n_in,
                              void* d_out, int out_size) {
    // Identify inputs by element count (ordering-proof).
    const float* x  = nullptr;   // node_states: 6,400,000
    const void*  ed = nullptr;   // edges:       1,600,000
    const float* W  = nullptr;   // kernel:         16,384
    const float* ka = nullptr;   // kernel_attention:  256
    for (int i = 0; i < n_in; i++) {
        switch (in_sizes[i]) {
            case 6400000: x  = (const float*)d_in[i]; break;
            case 1600000: ed = d_in[i];               break;
            case 16384:   W  = (const float*)d_in[i]; break;
            case 256:     ka = (const float*)d_in[i]; break;
            default: break;
        }
    }
    float* out = (float*)d_out;  // [50000,128] float32

    probe_kernel<<<1, 1024>>>((const int*)ed);
    rowptr_kernel<<<(N_EDGES + 255) / 256, 256>>>((const int*)ed);
    gemm_kernel<<<(N_NODES + BM - 1) / BM, 256>>>(x, W, ka);
    agg_kernel<<<(N_NODES * 32 + 255) / 256, 256>>>((const int*)ed, out);
}

// round 10
// speedup vs baseline: 1.5275x; 1.0756x over previous
#include <cuda_runtime.h>
#include <cuda_fp16.h>
#include <cstdint>

#define N_NODES 50000
#define N_EDGES 800000
#define D_FEAT  128

// Scratch (device globals — no allocation allowed)
__device__ __half g_hh[N_NODES * D_FEAT];     // 12.8 MB, L2-resident
__device__ float g_s1[N_NODES];
__device__ float g_s2[N_NODES];
__device__ float g_w[N_EDGES];                // 3.2 MB edge scores
__device__ int   g_rowptr[N_NODES + 1];
__device__ int   g_edges64;                   // 1 if edges are int64, 0 if int32

// ---------------------------------------------------------------------------
// probe: detect edge dtype. int64 values < 2^31 have all-zero odd words.
// ---------------------------------------------------------------------------
__global__ void probe_kernel(const int* __restrict__ w) {
    __shared__ int any_nonzero;
    if (threadIdx.x == 0) any_nonzero = 0;
    __syncthreads();
    if (w[2 * threadIdx.x + 1] != 0) atomicExch(&any_nonzero, 1);
    __syncthreads();
    if (threadIdx.x == 0) g_edges64 = any_nonzero ? 0 : 1;
}

// ---------------------------------------------------------------------------
// CSR rowptr from sorted src. rowptr[n] = first edge with src >= n.
// ---------------------------------------------------------------------------
__global__ void rowptr_kernel(const int* __restrict__ ew) {
    const int is64 = g_edges64;
    const int stride = is64 ? 4 : 2;
    int e = blockIdx.x * blockDim.x + threadIdx.x;
    if (e >= N_EDGES) return;
    int s  = ew[e * stride];
    int sp = (e == 0) ? -1 : ew[(e - 1) * stride];
    for (int n = sp + 1; n <= s; ++n) g_rowptr[n] = e;
    if (e == N_EDGES - 1)
        for (int n = s + 1; n <= N_NODES; ++n) g_rowptr[n] = N_EDGES;
}

// ---------------------------------------------------------------------------
// GEMM: h = X @ W via tf32 mma.sync.m16n8k8 (tensor pipe), h stored as fp16.
// Fused epilogue: s1[row] = h[row]·ka[0:128], s2[row] = h[row]·ka[128:256].
// PTX ISA fragment layout for m16n8k8 tf32 (g=lane>>2, tig=lane&3):
//   a0=(g,tig) a1=(g+8,tig) a2=(g,tig+4) a3=(g+8,tig+4)
//   b0=(k=tig,n=g) b1=(k=tig+4,n=g)
//   c0=(g,2tig) c1=(g,2tig+1) c2=(g+8,2tig) c3=(g+8,2tig+1)
// ---------------------------------------------------------------------------
#define BM 128
#define BK 32
#define XS_STRIDE 40    // A 32-bit LDS: banks 8g+tig all distinct
#define WS_STRIDE 136   // B 32-bit LDS: banks 8tig+g all distinct

__device__ __forceinline__ uint32_t f2tf(float f) {
    uint32_t r;
    asm("cvt.rna.tf32.f32 %0, %1;" : "=r"(r) : "f"(f));
    return r;
}

__device__ __forceinline__ void mma_tf32(float c[4], uint32_t a0, uint32_t a1,
                                         uint32_t a2, uint32_t a3,
                                         uint32_t b0, uint32_t b1) {
    asm volatile(
        "mma.sync.aligned.m16n8k8.row.col.f32.tf32.tf32.f32 "
        "{%0,%1,%2,%3}, {%4,%5,%6,%7}, {%8,%9}, {%0,%1,%2,%3};\n"
        : "+f"(c[0]), "+f"(c[1]), "+f"(c[2]), "+f"(c[3])
        : "r"(a0), "r"(a1), "r"(a2), "r"(a3), "r"(b0), "r"(b1));
}

__global__ __launch_bounds__(256, 1) void gemm_kernel(const float* __restrict__ x,
                                                      const float* __restrict__ W,
                                                      const float* __restrict__ ka) {
    __shared__ uint32_t Xs[BM * XS_STRIDE];   // 20 KB
    __shared__ uint32_t Ws[BK * WS_STRIDE];   // 17 KB
    __shared__ float    sp1[4][BM];           // 2 KB  per-warp s1 partials
    __shared__ float    sp2[4][BM];           // 2 KB  per-warp s2 partials
    const int tid  = threadIdx.x;
    const int lane = tid & 31;
    const int warp = tid >> 5;
    const int wm = warp >> 2;     // 0..1 : M quadrant (64 rows)
    const int wn = warp & 3;      // 0..3 : N quadrant (32 cols)
    const int g   = lane >> 2;    // groupID 0..7
    const int tig = lane & 3;     // threadID_in_group 0..3
    const int row0 = blockIdx.x * BM;

    float c[4][4][4];
#pragma unroll
    for (int mt = 0; mt < 4; mt++)
#pragma unroll
        for (int nt = 0; nt < 4; nt++)
#pragma unroll
            for (int r = 0; r < 4; r++) c[mt][nt][r] = 0.f;

    for (int kc = 0; kc < 4; ++kc) {
        // stage X tile [128 x 32] (tf32-converted)
#pragma unroll
        for (int i = 0; i < 4; i++) {
            int idx = tid + i * 256;
            int r = idx >> 3, c4 = (idx & 7) << 2;
            float4 v = make_float4(0.f, 0.f, 0.f, 0.f);
            if (row0 + r < N_NODES)
                v = *(const float4*)&x[(row0 + r) * D_FEAT + kc * BK + c4];
            uint32_t* p = &Xs[r * XS_STRIDE + c4];
            p[0] = f2tf(v.x); p[1] = f2tf(v.y); p[2] = f2tf(v.z); p[3] = f2tf(v.w);
        }
        // stage W tile [32 x 128]
#pragma unroll
        for (int i = 0; i < 4; i++) {
            int idx = tid + i * 256;
            int r = idx >> 5, c4 = (idx & 31) << 2;
            float4 v = *(const float4*)&W[(kc * BK + r) * D_FEAT + c4];
            uint32_t* p = &Ws[r * WS_STRIDE + c4];
            p[0] = f2tf(v.x); p[1] = f2tf(v.y); p[2] = f2tf(v.z); p[3] = f2tf(v.w);
        }
        __syncthreads();

#pragma unroll
        for (int ks = 0; ks < 4; ++ks) {
            const int k0 = ks * 8;
            uint32_t b[4][2];
#pragma unroll
            for (int nt = 0; nt < 4; nt++) {
                int n = wn * 32 + nt * 8 + g;
                b[nt][0] = Ws[(k0 + tig) * WS_STRIDE + n];
                b[nt][1] = Ws[(k0 + tig + 4) * WS_STRIDE + n];
            }
#pragma unroll
            for (int mt = 0; mt < 4; mt++) {
                int rb = wm * 64 + mt * 16;
                uint32_t a0 = Xs[(rb + g) * XS_STRIDE + k0 + tig];
                uint32_t a1 = Xs[(rb + g + 8) * XS_STRIDE + k0 + tig];
                uint32_t a2 = Xs[(rb + g) * XS_STRIDE + k0 + tig + 4];
                uint32_t a3 = Xs[(rb + g + 8) * XS_STRIDE + k0 + tig + 4];
#pragma unroll
                for (int nt = 0; nt < 4; nt++)
                    mma_tf32(c[mt][nt], a0, a1, a2, a3, b[nt][0], b[nt][1]);
            }
        }
        __syncthreads();
    }

    // per-lane attention-vector fragments: s = h · ka
    float2 wa1f[4], wa2f[4];
#pragma unroll
    for (int nt = 0; nt < 4; nt++) {
        int col = wn * 32 + nt * 8 + 2 * tig;
        wa1f[nt] = *(const float2*)&ka[col];           // a1 = ka[0:128]
        wa2f[nt] = *(const float2*)&ka[D_FEAT + col];  // a2 = ka[128:256]
    }

    // epilogue: write h as fp16 + accumulate s partials from fp32 accumulators
#pragma unroll
    for (int mt = 0; mt < 4; mt++) {
        float p1a = 0.f, p2a = 0.f;   // row wm*64+mt*16+g
        float p1b = 0.f, p2b = 0.f;   // row ... +8
#pragma unroll
        for (int nt = 0; nt < 4; nt++) {
            int r0 = row0 + wm * 64 + mt * 16 + g;
            int col = wn * 32 + nt * 8 + 2 * tig;
            if (r0 < N_NODES)
                *(__half2*)&g_hh[r0 * D_FEAT + col] =
                    __floats2half2_rn(c[mt][nt][0], c[mt][nt][1]);
            if (r0 + 8 < N_NODES)
                *(__half2*)&g_hh[(r0 + 8) * D_FEAT + col] =
                    __floats2half2_rn(c[mt][nt][2], c[mt][nt][3]);
            p1a += c[mt][nt][0] * wa1f[nt].x + c[mt][nt][1] * wa1f[nt].y;
            p2a += c[mt][nt][0] * wa2f[nt].x + c[mt][nt][1] * wa2f[nt].y;
            p1b += c[mt][nt][2] * wa1f[nt].x + c[mt][nt][3] * wa1f[nt].y;
            p2b += c[mt][nt][2] * wa2f[nt].x + c[mt][nt][3] * wa2f[nt].y;
        }
#pragma unroll
        for (int o = 1; o <= 2; o <<= 1) {
            p1a += __shfl_xor_sync(0xffffffffu, p1a, o);
            p2a += __shfl_xor_sync(0xffffffffu, p2a, o);
            p1b += __shfl_xor_sync(0xffffffffu, p1b, o);
            p2b += __shfl_xor_sync(0xffffffffu, p2b, o);
        }
        if (tig == 0) {
            int rl = wm * 64 + mt * 16 + g;
            sp1[wn][rl]     = p1a;  sp2[wn][rl]     = p2a;
            sp1[wn][rl + 8] = p1b;  sp2[wn][rl + 8] = p2b;
        }
    }
    __syncthreads();
    if (tid < BM) {
        int grow = row0 + tid;
        if (grow < N_NODES) {
            g_s1[grow] = sp1[0][tid] + sp1[1][tid] + sp1[2][tid] + sp1[3][tid];
            g_s2[grow] = sp2[0][tid] + sp2[1][tid] + sp2[2][tid] + sp2[3][tid];
        }
    }
}

// ---------------------------------------------------------------------------
// score: edge-parallel w[e] = exp(clip(leaky(s1[src]+s2[dst]))). Coalesced.
// ---------------------------------------------------------------------------
__global__ void score_kernel(const int* __restrict__ ew) {
    const int is64 = g_edges64;
    const int stride = is64 ? 4 : 2;
    const int doff   = is64 ? 2 : 1;
    int e = blockIdx.x * blockDim.x + threadIdx.x;
    if (e >= N_EDGES) return;
    int s = ew[e * stride];
    int d = ew[e * stride + doff];
    float l = g_s1[s] + g_s2[d];
    l = (l > 0.f) ? l : 0.2f * l;          // leaky_relu(0.2)
    l = fminf(fmaxf(l, -2.f), 2.f);        // clip
    g_w[e] = __expf(l);
}

// ---------------------------------------------------------------------------
// agg: TWO nodes per warp, 16 lanes each; lane owns 8 cols (one uint4 row
// slice). Scores precomputed -> inner loop is just w-load + gather + FMA.
// Denominator accumulated redundantly per half-warp (no reduce needed).
// ---------------------------------------------------------------------------
__device__ __forceinline__ void acc8(float4& a, float4& b, float w, uint4 r) {
    float2 f0 = __half22float2(*(__half2*)&r.x);
    float2 f1 = __half22float2(*(__half2*)&r.y);
    float2 f2 = __half22float2(*(__half2*)&r.z);
    float2 f3 = __half22float2(*(__half2*)&r.w);
    a.x += w * f0.x; a.y += w * f0.y; a.z += w * f1.x; a.w += w * f1.y;
    b.x += w * f2.x; b.y += w * f2.y; b.z += w * f3.x; b.w += w * f3.y;
}

__global__ void agg_kernel(const int* __restrict__ ew,
                           float* __restrict__ out) {
    const int is64 = g_edges64;
    const int stride = is64 ? 4 : 2;
    const int doff   = is64 ? 2 : 1;
    int t = blockIdx.x * blockDim.x + threadIdx.x;
    int warp = t >> 5, lane = t & 31;
    int hl = lane & 15;                    // lane within half-warp
    int node = (warp << 1) | (lane >> 4);  // 2 nodes per warp
    if (node >= N_NODES) return;
    const int e0 = g_rowptr[node];
    const int e1 = g_rowptr[node + 1];
    const __half* __restrict__ hc = g_hh + hl * 8;

    float4 accA = make_float4(0.f, 0.f, 0.f, 0.f);
    float4 accB = make_float4(0.f, 0.f, 0.f, 0.f);
    float denom = 0.f;
    int e = e0;
    for (; e + 2 <= e1; e += 2) {
        int d0 = ew[(e + 0) * stride + doff];
        int d1 = ew[(e + 1) * stride + doff];
        float w0 = g_w[e];
        float w1 = g_w[e + 1];
        uint4 r0 = *(const uint4*)&hc[d0 * D_FEAT];
        uint4 r1 = *(const uint4*)&hc[d1 * D_FEAT];
        denom += w0 + w1;
        acc8(accA, accB, w0, r0);
        acc8(accA, accB, w1, r1);
    }
    if (e < e1) {
        int d = ew[e * stride + doff];
        float w = g_w[e];
        uint4 r = *(const uint4*)&hc[d * D_FEAT];
        denom += w;
        acc8(accA, accB, w, r);
    }
    float rinv = (e1 > e0) ? (1.0f / denom) : 0.f;
    accA.x *= rinv; accA.y *= rinv; accA.z *= rinv; accA.w *= rinv;
    accB.x *= rinv; accB.y *= rinv; accB.z *= rinv; accB.w *= rinv;
    float* o = out + node * D_FEAT + hl * 8;
    *(float4*)o       = accA;
    *(float4*)(o + 4) = accB;
}

// ---------------------------------------------------------------------------
extern "C" void kernel_launch(void* const* d_in, const int* in_sizes, int n_in,
                              void* d_out, int out_size) {
    // Identify inputs by element count (ordering-proof).
    const float* x  = nullptr;   // node_states: 6,400,000
    const void*  ed = nullptr;   // edges:       1,600,000
    const float* W  = nullptr;   // kernel:         16,384
    const float* ka = nullptr;   // kernel_attention:  256
    for (int i = 0; i < n_in; i++) {
        switch (in_sizes[i]) {
            case 6400000: x  = (const float*)d_in[i]; break;
            case 1600000: ed = d_in[i];               break;
            case 16384:   W  = (const float*)d_in[i]; break;
            case 256:     ka = (const float*)d_in[i]; break;
            default: break;
        }
    }
    float* out = (float*)d_out;  // [50000,128] float32

    probe_kernel<<<1, 1024>>>((const int*)ed);
    rowptr_kernel<<<(N_EDGES + 255) / 256, 256>>>((const int*)ed);
    gemm_kernel<<<(N_NODES + BM - 1) / BM, 256>>>(x, W, ka);
    score_kernel<<<(N_EDGES + 255) / 256, 256>>>((const int*)ed);
    // 2 nodes/warp -> N_NODES/2 warps -> N_NODES*16 threads
    agg_kernel<<<(N_NODES * 16 + 255) / 256, 256>>>((const int*)ed, out);
}